// round 8
// baseline (speedup 1.0000x reference)
#include <cuda_runtime.h>

#define B 8
#define L 2048
#define H 8
#define D 64
#define S 40
#define U 40
#define NBH (B*H)
#define SPLIT 8
#define CHUNK (L/SPLIT)   // 256 (K5 key chunk)
#define KCH 256           // K1: key rows per chunk
#define NCH 8             // K1: key chunks
#define LCH 256           // K1: queries per block
#define NEG_INF (-3.4e38f)

typedef unsigned long long ull;

// ---------------- f32x2 helpers ----------------
__device__ __forceinline__ ull pk2(float a, float b) {
    ull r; asm("mov.b64 %0,{%1,%2};" : "=l"(r) : "f"(a), "f"(b)); return r;
}
__device__ __forceinline__ void upk2(ull v, float& a, float& b) {
    asm("mov.b64 {%0,%1},%2;" : "=f"(a), "=f"(b) : "l"(v));
}
__device__ __forceinline__ ull fma2_(ull a, ull b, ull c) {
    ull d; asm("fma.rn.f32x2 %0,%1,%2,%3;" : "=l"(d) : "l"(a), "l"(b), "l"(c)); return d;
}
__device__ __forceinline__ ull mul2_(ull a, ull b) {
    ull d; asm("mul.rn.f32x2 %0,%1,%2;" : "=l"(d) : "l"(a), "l"(b)); return d;
}
__device__ __forceinline__ ull add2_(ull a, ull b) {
    ull d; asm("add.rn.f32x2 %0,%1,%2;" : "=l"(d) : "l"(a), "l"(b)); return d;
}

// ---------------- scratch (device globals; no allocation) ----------------
__device__ int      g_bidx[L*S];          // chunk-bucketed sample indices (per l)
__device__ unsigned g_bmeta[L*NCH];       // (off<<16)|cnt per (l, chunk)
__device__ float    g_M[NBH*L];           // sparsity metric
__device__ int      g_Mtop[NBH*U];        // top-U query indices per bh
__device__ float    g_Vpart[NBH*SPLIT*D]; // partial V sums
__device__ float    g_pO[NBH*SPLIT*U*D];  // split attention partial outputs
__device__ float    g_pm[NBH*SPLIT*U];    // split local max
__device__ float    g_pl[NBH*SPLIT*U];    // split local sum-exp

// ---------------- K0: bucket each l's 40 sample indices by key-chunk ----------------
__global__ void __launch_bounds__(256) k0_bucket(const int* __restrict__ idxs) {
    int l = blockIdx.x * 256 + threadIdx.x;      // 2048 threads
    const int* p = idxs + l * S;
    int cnt[NCH];
    #pragma unroll
    for (int c = 0; c < NCH; c++) cnt[c] = 0;
    #pragma unroll
    for (int s = 0; s < S; s++) {
        int c = p[s] >> 8;
        #pragma unroll
        for (int cc = 0; cc < NCH; cc++) cnt[cc] += (c == cc);
    }
    int pos[NCH];
    int run = 0;
    #pragma unroll
    for (int c = 0; c < NCH; c++) {
        pos[c] = run;
        g_bmeta[l*NCH + c] = ((unsigned)run << 16) | (unsigned)cnt[c];
        run += cnt[c];
    }
    #pragma unroll
    for (int s = 0; s < S; s++) {
        int v = p[s];
        int c = v >> 8;
        #pragma unroll
        for (int cc = 0; cc < NCH; cc++) {
            if (c == cc) { g_bidx[l*S + pos[cc]] = v; pos[cc]++; }
        }
    }
}

// ---------------- K1: smem-tiled sampled dots ----------------
// block = (bh, l-chunk of 256 queries). smem: Q panel + K chunk + idx lists + meta + partials.
// warp = 4 groups x 8 lanes; group owns one query per round (4 l's per warp-round).
#define Q_OFF   0                         // 256*64 floats = 16384
#define KS_OFF  16384                     // 256*64 floats = 16384
#define IDX_OFF 32768                     // 256*40 ints  = 10240
#define MET_OFF 43008                     // 256*8 uints  = 2048
#define PMX_OFF 45056                     // 256 floats
#define PSM_OFF 45312                     // 256 floats
#define SMEM1_FLOATS 45568
#define SMEM1_BYTES (SMEM1_FLOATS*4)      // 182272 B

__global__ void __launch_bounds__(512, 1) k1_tile(const float* __restrict__ Qg,
                                                  const float* __restrict__ Kg) {
    int bh = blockIdx.x >> 3, lch = blockIdx.x & 7;
    int b = bh >> 3, h = bh & 7;
    int l0 = lch * LCH;
    int tid = threadIdx.x;
    extern __shared__ float sm[];
    float4*   Qs4  = (float4*)(sm + Q_OFF);
    float4*   Ks4  = (float4*)(sm + KS_OFF);
    int*      sidx = (int*)(sm + IDX_OFF);
    unsigned* smet = (unsigned*)(sm + MET_OFF);
    float*    pmx  = sm + PMX_OFF;
    float*    psm  = sm + PSM_OFF;

    // ---- stage Q panel (coalesced), idx lists, meta, init partials ----
    for (int e = tid; e < LCH*16; e += 512) {
        int i = e >> 4, c4 = e & 15;
        Qs4[e] = __ldg((const float4*)(Qg + ((size_t)(b*L + l0 + i)*H + h)*D) + c4);
    }
    for (int e = tid; e < LCH*S; e += 512) {
        int i = e / S, j = e - i*S;
        sidx[e] = g_bidx[(l0 + i)*S + j];
    }
    for (int e = tid; e < LCH*NCH; e += 512) smet[e] = g_bmeta[l0*NCH + e];
    if (tid < LCH) { pmx[tid] = NEG_INF; psm[tid] = 0.f; }
    __syncthreads();

    int lane = tid & 31, w = tid >> 5;
    int g = lane >> 3, s = lane & 7;
    unsigned gmask = 0xFFu << (g * 8);

    for (int c = 0; c < NCH; c++) {
        // stage K chunk (coalesced)
        const float* Kbase = Kg + (size_t)(b*L + c*KCH)*(H*D) + h*D;
        for (int e = tid; e < KCH*16; e += 512) {
            int kk = e >> 4, c4 = e & 15;
            Ks4[e] = __ldg((const float4*)(Kbase + (size_t)kk*(H*D)) + c4);
        }
        __syncthreads();

        #pragma unroll
        for (int rr = 0; rr < 4; rr++) {
            int lloc = w*16 + rr*4 + g;               // group's query
            unsigned mt = smet[lloc*NCH + c];
            int cnt = (int)(mt & 0xffffu);
            if (cnt) {
                int off = (int)(mt >> 16);
                const float4* qp = Qs4 + lloc*16;
                float4 qa = qp[s], qb = qp[s + 8];    // group-aligned phases: conflict-free
                ull q0 = pk2(qa.x, qa.y), q1 = pk2(qa.z, qa.w);
                ull q2 = pk2(qb.x, qb.y), q3 = pk2(qb.z, qb.w);
                const int* ip = sidx + lloc*S + off;
                float gmax = NEG_INF, gsum = 0.f;
                for (int j = 0; j < cnt; j++) {
                    int row = ip[j] & 255;            // broadcast within group
                    const float4* kp = Ks4 + row*16;
                    float4 ka = kp[s], kb = kp[s + 8];
                    ull a0 = mul2_(q0, pk2(ka.x, ka.y));
                    ull a1 = mul2_(q1, pk2(ka.z, ka.w));
                    a0 = fma2_(q2, pk2(kb.x, kb.y), a0);
                    a1 = fma2_(q3, pk2(kb.z, kb.w), a1);
                    a0 = add2_(a0, a1);
                    float lo, hi; upk2(a0, lo, hi);
                    float p = lo + hi;
                    p += __shfl_xor_sync(gmask, p, 1);
                    p += __shfl_xor_sync(gmask, p, 2);
                    p += __shfl_xor_sync(gmask, p, 4);
                    gmax = fmaxf(gmax, p);
                    gsum += p;
                }
                if (s == 0) {                          // sole owner of lloc this chunk
                    pmx[lloc] = fmaxf(pmx[lloc], gmax);
                    psm[lloc] += gsum;
                }
            }
        }
        __syncthreads();
    }

    if (tid < LCH)
        g_M[bh*L + l0 + tid] = pmx[tid] - psm[tid] * (1.0f / S);
}

// ---------------- K2: top-U per bh via iterative argmax ----------------
__global__ void __launch_bounds__(256) k2_topk() {
    __shared__ float sv[L];
    __shared__ float rv[8];
    __shared__ int   ri[8];
    int bh = blockIdx.x, tid = threadIdx.x;
    for (int i = tid; i < L; i += 256) sv[i] = g_M[bh*L + i];
    __syncthreads();
    for (int it = 0; it < U; it++) {
        float v = NEG_INF; int id = 0;
        for (int i = tid; i < L; i += 256) {
            float x = sv[i];
            if (x > v) { v = x; id = i; }
        }
        for (int o = 16; o; o >>= 1) {
            float ov = __shfl_down_sync(0xffffffffu, v, o);
            int   oi = __shfl_down_sync(0xffffffffu, id, o);
            if (ov > v || (ov == v && oi < id)) { v = ov; id = oi; }
        }
        if ((tid & 31) == 0) { rv[tid >> 5] = v; ri[tid >> 5] = id; }
        __syncthreads();
        if (tid == 0) {
            float bv = rv[0]; int bi = ri[0];
            #pragma unroll
            for (int w = 1; w < 8; w++)
                if (rv[w] > bv || (rv[w] == bv && ri[w] < bi)) { bv = rv[w]; bi = ri[w]; }
            g_Mtop[bh*U + it] = bi;
            sv[bi] = NEG_INF;
        }
        __syncthreads();
    }
}

// ---------------- K3: partial V sums over L-chunks ----------------
__global__ void __launch_bounds__(256) k3_vsum(const float* __restrict__ Vg) {
    int bh = blockIdx.x >> 3, sp = blockIdx.x & 7;
    int b = bh >> 3, h = bh & 7;
    int d  = threadIdx.x & 63;
    int lg = threadIdx.x >> 6;
    const float* base = Vg + (size_t)b*L*(H*D) + h*D + d;
    int l0 = sp*CHUNK + lg;
    float a0 = 0.f, a1 = 0.f;
    #pragma unroll 8
    for (int i = 0; i < CHUNK/8; i++) {
        a0 += base[(size_t)(l0 + i*8    ) * (H*D)];
        a1 += base[(size_t)(l0 + i*8 + 4) * (H*D)];
    }
    __shared__ float red[4][64];
    red[lg][d] = a0 + a1;
    __syncthreads();
    if (threadIdx.x < 64)
        g_Vpart[(bh*SPLIT + sp)*D + threadIdx.x] =
            red[0][threadIdx.x] + red[1][threadIdx.x] + red[2][threadIdx.x] + red[3][threadIdx.x];
}

// ---------------- K4: broadcast V-mean into full output ----------------
__global__ void __launch_bounds__(256) k4_fill(float* __restrict__ out) {
    int b  = blockIdx.x >> 6;
    int r0 = (blockIdx.x & 63) * 32;
    __shared__ __align__(16) float vec[512];
    int tid = threadIdx.x;
    for (int j = tid; j < 512; j += 256) {
        int h = j >> 6, d = j & 63;
        float s = 0.f;
        #pragma unroll
        for (int sp = 0; sp < SPLIT; sp++)
            s += g_Vpart[((b*H + h)*SPLIT + sp)*D + d];
        vec[j] = s * (1.0f / L);
    }
    __syncthreads();
    float4* o4 = (float4*)(out + (size_t)(b*L + r0) * (H*D));
    const float4* v4 = (const float4*)vec;
    for (int e = tid; e < 32*128; e += 256) {
        int r = e >> 7, c = e & 127;
        o4[r*128 + c] = v4[c];
    }
}

// ---------------- K5: split-K sparse attention partials (round-1 proven) ----------------
#define SM_QS 0
#define SM_KS 2560
#define SM_SC (2560 + 16384)
#define SMEM5_BYTES ((2560 + 16384 + 10240) * 4)

__global__ void __launch_bounds__(256) k5_attn(const float* __restrict__ Qg,
                                               const float* __restrict__ Kg,
                                               const float* __restrict__ Vg) {
    int bh = blockIdx.x >> 3, sp = blockIdx.x & 7;
    int b = bh >> 3, h = bh & 7;
    int tid = threadIdx.x;
    extern __shared__ float sm[];
    float* Qs = sm + SM_QS;
    float* Ks = sm + SM_KS;
    float* Sc = sm + SM_SC;
    __shared__ int topq[U];

    if (tid < U) topq[tid] = g_Mtop[bh*U + tid];
    __syncthreads();

    for (int e = tid; e < U*D; e += 256) {
        int i = e >> 6, d = e & 63;
        Qs[e] = Qg[((size_t)(b*L + topq[i])*H + h)*D + d];
    }
    const float* Kbase = Kg + (size_t)(b*L + sp*CHUNK)*(H*D) + h*D;
    for (int e = tid; e < CHUNK*D; e += 256) {
        int kk = e >> 6, d = e & 63;
        Ks[kk*64 + (d ^ (kk >> 3))] = Kbase[(size_t)kk*(H*D) + d];
    }
    __syncthreads();

    int qg = tid >> 5, kg = tid & 31;
    float acc[5][8];
    #pragma unroll
    for (int i = 0; i < 5; i++)
        #pragma unroll
        for (int j = 0; j < 8; j++) acc[i][j] = 0.f;

    for (int d = 0; d < D; d++) {
        float qv[5], kv[8];
        #pragma unroll
        for (int i = 0; i < 5; i++) qv[i] = Qs[(qg*5 + i)*64 + d];
        #pragma unroll
        for (int j = 0; j < 8; j++) kv[j] = Ks[(kg*8 + j)*64 + (d ^ kg)];
        #pragma unroll
        for (int i = 0; i < 5; i++)
            #pragma unroll
            for (int j = 0; j < 8; j++) acc[i][j] = fmaf(qv[i], kv[j], acc[i][j]);
    }
    #pragma unroll
    for (int i = 0; i < 5; i++) {
        int q = qg*5 + i;
        #pragma unroll
        for (int j = 0; j < 8; j++) {
            int kk = kg*8 + j;
            Sc[q*256 + (kk ^ (q & 31))] = acc[i][j] * 0.125f;
        }
    }
    __syncthreads();

    const float* Vbase = Vg + (size_t)(b*L + sp*CHUNK)*(H*D) + h*D;
    for (int e = tid; e < CHUNK*D; e += 256) {
        int kk = e >> 6, d = e & 63;
        Ks[kk*64 + (d ^ (kk >> 3))] = Vbase[(size_t)kk*(H*D) + d];
    }

    int lane = tid & 31;
    #pragma unroll
    for (int i = 0; i < 5; i++) {
        int q = qg*5 + i;
        float vals[8];
        float mv = NEG_INF;
        #pragma unroll
        for (int t = 0; t < 8; t++) {
            int kk = lane + t*32;
            vals[t] = Sc[q*256 + (kk ^ (q & 31))];
            mv = fmaxf(mv, vals[t]);
        }
        #pragma unroll
        for (int o = 16; o; o >>= 1) mv = fmaxf(mv, __shfl_xor_sync(0xffffffffu, mv, o));
        float ssum = 0.f;
        #pragma unroll
        for (int t = 0; t < 8; t++) {
            int kk = lane + t*32;
            float ev = __expf(vals[t] - mv);
            Sc[q*256 + (kk ^ (q & 31))] = ev;
            ssum += ev;
        }
        #pragma unroll
        for (int o = 16; o; o >>= 1) ssum += __shfl_xor_sync(0xffffffffu, ssum, o);
        if (lane == 0) {
            g_pm[(bh*SPLIT + sp)*U + q] = mv;
            g_pl[(bh*SPLIT + sp)*U + q] = ssum;
        }
    }
    __syncthreads();

    int kr  = tid >> 6;
    int r   = tid & 63;
    int qg2 = r >> 3, dg = r & 7;
    float facc[5][8];
    #pragma unroll
    for (int i = 0; i < 5; i++)
        #pragma unroll
        for (int j = 0; j < 8; j++) facc[i][j] = 0.f;

    for (int kl = 0; kl < 64; kl++) {
        int kk = kr*64 + kl;
        float pv[5], vv[8];
        #pragma unroll
        for (int i = 0; i < 5; i++) {
            int q = qg2*5 + i;
            pv[i] = Sc[q*256 + (kk ^ (q & 31))];
        }
        #pragma unroll
        for (int j = 0; j < 8; j++) {
            int d = dg*8 + j;
            vv[j] = Ks[kk*64 + (d ^ (kk >> 3))];
        }
        #pragma unroll
        for (int i = 0; i < 5; i++)
            #pragma unroll
            for (int j = 0; j < 8; j++) facc[i][j] = fmaf(pv[i], vv[j], facc[i][j]);
    }
    __syncthreads();
    #pragma unroll
    for (int i = 0; i < 5; i++) {
        int q = qg2*5 + i;
        #pragma unroll
        for (int j = 0; j < 8; j++) {
            int d = dg*8 + j;
            Sc[kr*2560 + q*64 + d] = facc[i][j];
        }
    }
    __syncthreads();
    for (int e = tid; e < U*D; e += 256) {
        float s = Sc[e] + Sc[2560 + e] + Sc[5120 + e] + Sc[7680 + e];
        g_pO[(size_t)(bh*SPLIT + sp)*U*D + e] = s;
    }
}

// ---------------- K6: combine splits + scatter to output ----------------
__global__ void __launch_bounds__(256) k6_combine(float* __restrict__ out) {
    int bh = blockIdx.x;
    int b = bh >> 3, h = bh & 7;
    __shared__ float w[U*SPLIT];
    __shared__ int topq[U];
    int tid = threadIdx.x;
    if (tid < U) {
        topq[tid] = g_Mtop[bh*U + tid];
        float pm_[SPLIT], pl_[SPLIT];
        float m = NEG_INF;
        #pragma unroll
        for (int sp = 0; sp < SPLIT; sp++) {
            pm_[sp] = g_pm[(bh*SPLIT + sp)*U + tid];
            pl_[sp] = g_pl[(bh*SPLIT + sp)*U + tid];
            m = fmaxf(m, pm_[sp]);
        }
        float denom = 0.f, e_[SPLIT];
        #pragma unroll
        for (int sp = 0; sp < SPLIT; sp++) {
            e_[sp] = __expf(pm_[sp] - m);
            denom += pl_[sp] * e_[sp];
        }
        float inv = 1.0f / denom;
        #pragma unroll
        for (int sp = 0; sp < SPLIT; sp++) w[tid*SPLIT + sp] = e_[sp] * inv;
    }
    __syncthreads();
    for (int e = tid; e < U*D; e += 256) {
        int q = e >> 6, d = e & 63;
        float s = 0.f;
        #pragma unroll
        for (int sp = 0; sp < SPLIT; sp++)
            s += g_pO[((size_t)(bh*SPLIT + sp)*U + q)*D + d] * w[q*SPLIT + sp];
        out[((size_t)(b*L + topq[q])*H + h)*D + d] = s;
    }
}

// ---------------- launch ----------------
extern "C" void kernel_launch(void* const* d_in, const int* in_sizes, int n_in,
                              void* d_out, int out_size) {
    const float* Q   = (const float*)d_in[0];
    const float* K   = (const float*)d_in[1];
    const float* V   = (const float*)d_in[2];
    const int*  idxs = (const int*)d_in[3];
    float* out = (float*)d_out;

    cudaFuncSetAttribute(k1_tile, cudaFuncAttributeMaxDynamicSharedMemorySize, SMEM1_BYTES);
    cudaFuncSetAttribute(k5_attn, cudaFuncAttributeMaxDynamicSharedMemorySize, SMEM5_BYTES);

    // k1 positioned as 4th launch so the ncu capture slot profiles it
    k0_bucket <<<L/256,     256>>>(idxs);
    k3_vsum   <<<NBH*SPLIT, 256>>>(V);
    k4_fill   <<<B*64,      256>>>(out);
    k1_tile   <<<NBH*8,     512, SMEM1_BYTES>>>(Q, K);
    k2_topk   <<<NBH,       256>>>();
    k5_attn   <<<NBH*SPLIT, 256, SMEM5_BYTES>>>(Q, K, V);
    k6_combine<<<NBH,       256>>>(out);
}

// round 9
// speedup vs baseline: 1.9633x; 1.9633x over previous
#include <cuda_runtime.h>

#define B 8
#define L 2048
#define H 8
#define D 64
#define S 40
#define U 40
#define NBH (B*H)
#define SPLIT 8
#define CHUNK (L/SPLIT)   // 256 (K5 key chunk)
#define KCH 256           // K1: key rows per chunk
#define NCH 8             // K1: key chunks
#define LCH 256           // K1: queries per block
#define NEG_INF (-3.4e38f)

typedef unsigned long long ull;
typedef unsigned int uint;

// ---------------- f32x2 helpers ----------------
__device__ __forceinline__ ull pk2(float a, float b) {
    ull r; asm("mov.b64 %0,{%1,%2};" : "=l"(r) : "f"(a), "f"(b)); return r;
}
__device__ __forceinline__ void upk2(ull v, float& a, float& b) {
    asm("mov.b64 {%0,%1},%2;" : "=f"(a), "=f"(b) : "l"(v));
}
__device__ __forceinline__ ull fma2_(ull a, ull b, ull c) {
    ull d; asm("fma.rn.f32x2 %0,%1,%2,%3;" : "=l"(d) : "l"(a), "l"(b), "l"(c)); return d;
}
__device__ __forceinline__ ull add2_(ull a, ull b) {
    ull d; asm("add.rn.f32x2 %0,%1,%2;" : "=l"(d) : "l"(a), "l"(b)); return d;
}

// ---------------- scratch (device globals; no allocation) ----------------
__device__ uint     g_bidxw[L*S/4];       // per-l sample rows as bytes, sorted by chunk
__device__ uint     g_bcntw[L*2];         // per-l 8 chunk counts as bytes
__device__ float    g_M[NBH*L];           // sparsity metric
__device__ int      g_Mtop[NBH*U];        // top-U query indices per bh
__device__ float    g_Vpart[NBH*SPLIT*D]; // partial V sums
__device__ float    g_pO[NBH*SPLIT*U*D];  // split attention partial outputs
__device__ float    g_pm[NBH*SPLIT*U];    // split local max
__device__ float    g_pl[NBH*SPLIT*U];    // split local sum-exp

// ---------------- K0: bucket each l's 40 sample indices by key-chunk (byte form) ----------------
__global__ void __launch_bounds__(256) k0_bucket(const int* __restrict__ idxs) {
    int l = blockIdx.x * 256 + threadIdx.x;      // 2048 threads
    const int* p = idxs + l * S;
    int cnt[NCH];
    #pragma unroll
    for (int c = 0; c < NCH; c++) cnt[c] = 0;
    #pragma unroll
    for (int s = 0; s < S; s++) {
        int c = p[s] >> 8;
        #pragma unroll
        for (int cc = 0; cc < NCH; cc++) cnt[cc] += (c == cc);
    }
    int pos[NCH];
    int run = 0;
    #pragma unroll
    for (int c = 0; c < NCH; c++) { pos[c] = run; run += cnt[c]; }
    g_bcntw[l*2    ] = (uint)cnt[0] | ((uint)cnt[1] << 8) | ((uint)cnt[2] << 16) | ((uint)cnt[3] << 24);
    g_bcntw[l*2 + 1] = (uint)cnt[4] | ((uint)cnt[5] << 8) | ((uint)cnt[6] << 16) | ((uint)cnt[7] << 24);
    unsigned char* bp = (unsigned char*)g_bidxw + l*S;
    #pragma unroll
    for (int s = 0; s < S; s++) {
        int v = p[s];
        int c = v >> 8;
        #pragma unroll
        for (int cc = 0; cc < NCH; cc++) {
            if (c == cc) { bp[pos[cc]] = (unsigned char)(v & 255); pos[cc]++; }
        }
    }
}

// ---------------- K1: thread-per-query, Q in registers, smem K chunks ----------------
// block = (bh, 256-query panel). smem: K chunk (64KB, also Q-panel bounce) + idx bytes (10KB)
#define SMEM1_BYTES (KCH*D*4 + LCH*S)   // 65536 + 10240 = 75776

__global__ void __launch_bounds__(256, 2) k1_reg(const float* __restrict__ Qg,
                                                 const float* __restrict__ Kg) {
    int bh = blockIdx.x >> 3, lch = blockIdx.x & 7;
    int b = bh >> 3, h = bh & 7;
    int l0 = lch * LCH;
    int t = threadIdx.x, lane = t & 31;
    extern __shared__ float sm[];
    float4* Ks4 = (float4*)sm;                          // 256 rows x 16 float4
    unsigned char* sByte = (unsigned char*)(sm + KCH*D); // 256 x 40 bytes

    // lane-rotated column order (bank-conflict-free for arbitrary rows)
    int offs[16];
    #pragma unroll
    for (int j = 0; j < 16; j++) offs[j] = (lane + j) & 15;

    // ---- stage Q panel into Ks4 (coalesced), idx bytes into sByte ----
    for (int e = t; e < LCH*16; e += 256) {
        int i = e >> 4, c4 = e & 15;
        Ks4[e] = __ldg((const float4*)(Qg + ((size_t)(b*L + l0 + i)*H + h)*D) + c4);
    }
    uint* sb32 = (uint*)sByte;
    for (int e = t; e < LCH*(S/4); e += 256)
        sb32[e] = g_bidxw[l0*(S/4) + e];
    __syncthreads();

    // own Q row -> registers, pre-rotated to match offs[]
    ull q0[16], q1[16];
    #pragma unroll
    for (int j = 0; j < 16; j++) {
        float4 v = Ks4[t*16 + offs[j]];
        q0[j] = pk2(v.x, v.y);
        q1[j] = pk2(v.z, v.w);
    }
    uint cw0 = g_bcntw[(l0 + t)*2];
    uint cw1 = g_bcntw[(l0 + t)*2 + 1];
    __syncthreads();

    ull z = pk2(0.f, 0.f);
    float lmax = NEG_INF, lsum = 0.f;
    int p0 = t * S;   // this thread's byte list base

    for (int c = 0; c < NCH; c++) {
        // stage K chunk (coalesced)
        const float* Kbase = Kg + (size_t)(b*L + c*KCH)*(H*D) + h*D;
        for (int e = t; e < KCH*16; e += 256) {
            int kk = e >> 4, c4 = e & 15;
            Ks4[e] = __ldg((const float4*)(Kbase + (size_t)kk*(H*D)) + c4);
        }
        __syncthreads();

        int cnt = (c < 4) ? (int)((cw0 >> (c*8)) & 255u)
                          : (int)((cw1 >> ((c-4)*8)) & 255u);
        for (int j = 0; j < cnt; j++) {
            int row = sByte[p0 + j];
            const float4* kp = Ks4 + row*16;
            ull a0 = z, a1 = z, a2 = z, a3 = z;
            #pragma unroll
            for (int jj = 0; jj < 16; jj += 2) {
                float4 ka = kp[offs[jj]];
                float4 kb = kp[offs[jj + 1]];
                a0 = fma2_(q0[jj],     pk2(ka.x, ka.y), a0);
                a1 = fma2_(q1[jj],     pk2(ka.z, ka.w), a1);
                a2 = fma2_(q0[jj + 1], pk2(kb.x, kb.y), a2);
                a3 = fma2_(q1[jj + 1], pk2(kb.z, kb.w), a3);
            }
            a0 = add2_(a0, a1); a2 = add2_(a2, a3); a0 = add2_(a0, a2);
            float lo, hi; upk2(a0, lo, hi);
            float pdot = lo + hi;
            lmax = fmaxf(lmax, pdot);
            lsum += pdot;
        }
        p0 += cnt;
        __syncthreads();
    }

    g_M[bh*L + l0 + t] = lmax - lsum * (1.0f / S);
}

// ---------------- K2: top-U per bh via iterative argmax ----------------
__global__ void __launch_bounds__(256) k2_topk() {
    __shared__ float sv[L];
    __shared__ float rv[8];
    __shared__ int   ri[8];
    int bh = blockIdx.x, tid = threadIdx.x;
    for (int i = tid; i < L; i += 256) sv[i] = g_M[bh*L + i];
    __syncthreads();
    for (int it = 0; it < U; it++) {
        float v = NEG_INF; int id = 0;
        for (int i = tid; i < L; i += 256) {
            float x = sv[i];
            if (x > v) { v = x; id = i; }
        }
        for (int o = 16; o; o >>= 1) {
            float ov = __shfl_down_sync(0xffffffffu, v, o);
            int   oi = __shfl_down_sync(0xffffffffu, id, o);
            if (ov > v || (ov == v && oi < id)) { v = ov; id = oi; }
        }
        if ((tid & 31) == 0) { rv[tid >> 5] = v; ri[tid >> 5] = id; }
        __syncthreads();
        if (tid == 0) {
            float bv = rv[0]; int bi = ri[0];
            #pragma unroll
            for (int w = 1; w < 8; w++)
                if (rv[w] > bv || (rv[w] == bv && ri[w] < bi)) { bv = rv[w]; bi = ri[w]; }
            g_Mtop[bh*U + it] = bi;
            sv[bi] = NEG_INF;
        }
        __syncthreads();
    }
}

// ---------------- K3: partial V sums over L-chunks ----------------
__global__ void __launch_bounds__(256) k3_vsum(const float* __restrict__ Vg) {
    int bh = blockIdx.x >> 3, sp = blockIdx.x & 7;
    int b = bh >> 3, h = bh & 7;
    int d  = threadIdx.x & 63;
    int lg = threadIdx.x >> 6;
    const float* base = Vg + (size_t)b*L*(H*D) + h*D + d;
    int l0 = sp*CHUNK + lg;
    float a0 = 0.f, a1 = 0.f;
    #pragma unroll 8
    for (int i = 0; i < CHUNK/8; i++) {
        a0 += base[(size_t)(l0 + i*8    ) * (H*D)];
        a1 += base[(size_t)(l0 + i*8 + 4) * (H*D)];
    }
    __shared__ float red[4][64];
    red[lg][d] = a0 + a1;
    __syncthreads();
    if (threadIdx.x < 64)
        g_Vpart[(bh*SPLIT + sp)*D + threadIdx.x] =
            red[0][threadIdx.x] + red[1][threadIdx.x] + red[2][threadIdx.x] + red[3][threadIdx.x];
}

// ---------------- K4: broadcast V-mean into full output ----------------
__global__ void __launch_bounds__(256) k4_fill(float* __restrict__ out) {
    int b  = blockIdx.x >> 6;
    int r0 = (blockIdx.x & 63) * 32;
    __shared__ __align__(16) float vec[512];
    int tid = threadIdx.x;
    for (int j = tid; j < 512; j += 256) {
        int h = j >> 6, d = j & 63;
        float s = 0.f;
        #pragma unroll
        for (int sp = 0; sp < SPLIT; sp++)
            s += g_Vpart[((b*H + h)*SPLIT + sp)*D + d];
        vec[j] = s * (1.0f / L);
    }
    __syncthreads();
    float4* o4 = (float4*)(out + (size_t)(b*L + r0) * (H*D));
    const float4* v4 = (const float4*)vec;
    for (int e = tid; e < 32*128; e += 256) {
        int r = e >> 7, c = e & 127;
        o4[r*128 + c] = v4[c];
    }
}

// ---------------- K5: split-K sparse attention partials (round-1 proven) ----------------
#define SM_QS 0
#define SM_KS 2560
#define SM_SC (2560 + 16384)
#define SMEM5_BYTES ((2560 + 16384 + 10240) * 4)

__global__ void __launch_bounds__(256) k5_attn(const float* __restrict__ Qg,
                                               const float* __restrict__ Kg,
                                               const float* __restrict__ Vg) {
    int bh = blockIdx.x >> 3, sp = blockIdx.x & 7;
    int b = bh >> 3, h = bh & 7;
    int tid = threadIdx.x;
    extern __shared__ float sm[];
    float* Qs = sm + SM_QS;
    float* Ks = sm + SM_KS;
    float* Sc = sm + SM_SC;
    __shared__ int topq[U];

    if (tid < U) topq[tid] = g_Mtop[bh*U + tid];
    __syncthreads();

    for (int e = tid; e < U*D; e += 256) {
        int i = e >> 6, d = e & 63;
        Qs[e] = Qg[((size_t)(b*L + topq[i])*H + h)*D + d];
    }
    const float* Kbase = Kg + (size_t)(b*L + sp*CHUNK)*(H*D) + h*D;
    for (int e = tid; e < CHUNK*D; e += 256) {
        int kk = e >> 6, d = e & 63;
        Ks[kk*64 + (d ^ (kk >> 3))] = Kbase[(size_t)kk*(H*D) + d];
    }
    __syncthreads();

    int qg = tid >> 5, kg = tid & 31;
    float acc[5][8];
    #pragma unroll
    for (int i = 0; i < 5; i++)
        #pragma unroll
        for (int j = 0; j < 8; j++) acc[i][j] = 0.f;

    for (int d = 0; d < D; d++) {
        float qv[5], kv[8];
        #pragma unroll
        for (int i = 0; i < 5; i++) qv[i] = Qs[(qg*5 + i)*64 + d];
        #pragma unroll
        for (int j = 0; j < 8; j++) kv[j] = Ks[(kg*8 + j)*64 + (d ^ kg)];
        #pragma unroll
        for (int i = 0; i < 5; i++)
            #pragma unroll
            for (int j = 0; j < 8; j++) acc[i][j] = fmaf(qv[i], kv[j], acc[i][j]);
    }
    #pragma unroll
    for (int i = 0; i < 5; i++) {
        int q = qg*5 + i;
        #pragma unroll
        for (int j = 0; j < 8; j++) {
            int kk = kg*8 + j;
            Sc[q*256 + (kk ^ (q & 31))] = acc[i][j] * 0.125f;
        }
    }
    __syncthreads();

    const float* Vbase = Vg + (size_t)(b*L + sp*CHUNK)*(H*D) + h*D;
    for (int e = tid; e < CHUNK*D; e += 256) {
        int kk = e >> 6, d = e & 63;
        Ks[kk*64 + (d ^ (kk >> 3))] = Vbase[(size_t)kk*(H*D) + d];
    }

    int lane = tid & 31;
    #pragma unroll
    for (int i = 0; i < 5; i++) {
        int q = qg*5 + i;
        float vals[8];
        float mv = NEG_INF;
        #pragma unroll
        for (int t = 0; t < 8; t++) {
            int kk = lane + t*32;
            vals[t] = Sc[q*256 + (kk ^ (q & 31))];
            mv = fmaxf(mv, vals[t]);
        }
        #pragma unroll
        for (int o = 16; o; o >>= 1) mv = fmaxf(mv, __shfl_xor_sync(0xffffffffu, mv, o));
        float ssum = 0.f;
        #pragma unroll
        for (int t = 0; t < 8; t++) {
            int kk = lane + t*32;
            float ev = __expf(vals[t] - mv);
            Sc[q*256 + (kk ^ (q & 31))] = ev;
            ssum += ev;
        }
        #pragma unroll
        for (int o = 16; o; o >>= 1) ssum += __shfl_xor_sync(0xffffffffu, ssum, o);
        if (lane == 0) {
            g_pm[(bh*SPLIT + sp)*U + q] = mv;
            g_pl[(bh*SPLIT + sp)*U + q] = ssum;
        }
    }
    __syncthreads();

    int kr  = tid >> 6;
    int r   = tid & 63;
    int qg2 = r >> 3, dg = r & 7;
    float facc[5][8];
    #pragma unroll
    for (int i = 0; i < 5; i++)
        #pragma unroll
        for (int j = 0; j < 8; j++) facc[i][j] = 0.f;

    for (int kl = 0; kl < 64; kl++) {
        int kk = kr*64 + kl;
        float pv[5], vv[8];
        #pragma unroll
        for (int i = 0; i < 5; i++) {
            int q = qg2*5 + i;
            pv[i] = Sc[q*256 + (kk ^ (q & 31))];
        }
        #pragma unroll
        for (int j = 0; j < 8; j++) {
            int d = dg*8 + j;
            vv[j] = Ks[kk*64 + (d ^ (kk >> 3))];
        }
        #pragma unroll
        for (int i = 0; i < 5; i++)
            #pragma unroll
            for (int j = 0; j < 8; j++) facc[i][j] = fmaf(pv[i], vv[j], facc[i][j]);
    }
    __syncthreads();
    #pragma unroll
    for (int i = 0; i < 5; i++) {
        int q = qg2*5 + i;
        #pragma unroll
        for (int j = 0; j < 8; j++) {
            int d = dg*8 + j;
            Sc[kr*2560 + q*64 + d] = facc[i][j];
        }
    }
    __syncthreads();
    for (int e = tid; e < U*D; e += 256) {
        float s = Sc[e] + Sc[2560 + e] + Sc[5120 + e] + Sc[7680 + e];
        g_pO[(size_t)(bh*SPLIT + sp)*U*D + e] = s;
    }
}

// ---------------- K6: combine splits + scatter to output ----------------
__global__ void __launch_bounds__(256) k6_combine(float* __restrict__ out) {
    int bh = blockIdx.x;
    int b = bh >> 3, h = bh & 7;
    __shared__ float w[U*SPLIT];
    __shared__ int topq[U];
    int tid = threadIdx.x;
    if (tid < U) {
        topq[tid] = g_Mtop[bh*U + tid];
        float pm_[SPLIT], pl_[SPLIT];
        float m = NEG_INF;
        #pragma unroll
        for (int sp = 0; sp < SPLIT; sp++) {
            pm_[sp] = g_pm[(bh*SPLIT + sp)*U + tid];
            pl_[sp] = g_pl[(bh*SPLIT + sp)*U + tid];
            m = fmaxf(m, pm_[sp]);
        }
        float denom = 0.f, e_[SPLIT];
        #pragma unroll
        for (int sp = 0; sp < SPLIT; sp++) {
            e_[sp] = __expf(pm_[sp] - m);
            denom += pl_[sp] * e_[sp];
        }
        float inv = 1.0f / denom;
        #pragma unroll
        for (int sp = 0; sp < SPLIT; sp++) w[tid*SPLIT + sp] = e_[sp] * inv;
    }
    __syncthreads();
    for (int e = tid; e < U*D; e += 256) {
        int q = e >> 6, d = e & 63;
        float s = 0.f;
        #pragma unroll
        for (int sp = 0; sp < SPLIT; sp++)
            s += g_pO[((size_t)(bh*SPLIT + sp)*U + q)*D + d] * w[q*SPLIT + sp];
        out[((size_t)(b*L + topq[q])*H + h)*D + d] = s;
    }
}

// ---------------- launch ----------------
extern "C" void kernel_launch(void* const* d_in, const int* in_sizes, int n_in,
                              void* d_out, int out_size) {
    const float* Q   = (const float*)d_in[0];
    const float* K   = (const float*)d_in[1];
    const float* V   = (const float*)d_in[2];
    const int*  idxs = (const int*)d_in[3];
    float* out = (float*)d_out;

    cudaFuncSetAttribute(k1_reg,  cudaFuncAttributeMaxDynamicSharedMemorySize, SMEM1_BYTES);
    cudaFuncSetAttribute(k5_attn, cudaFuncAttributeMaxDynamicSharedMemorySize, SMEM5_BYTES);

    // k1 positioned as 4th launch so the ncu capture slot profiles it
    k0_bucket <<<L/256,     256>>>(idxs);
    k3_vsum   <<<NBH*SPLIT, 256>>>(V);
    k4_fill   <<<B*64,      256>>>(out);
    k1_reg    <<<NBH*8,     256, SMEM1_BYTES>>>(Q, K);
    k2_topk   <<<NBH,       256>>>();
    k5_attn   <<<NBH*SPLIT, 256, SMEM5_BYTES>>>(Q, K, V);
    k6_combine<<<NBH,       256>>>(out);
}

// round 10
// speedup vs baseline: 2.7475x; 1.3995x over previous
#include <cuda_runtime.h>

#define B 8
#define L 2048
#define H 8
#define D 64
#define S 40
#define U 40
#define NBH (B*H)
#define SPLIT 8
#define CHUNK (L/SPLIT)   // 256 (K5 key chunk)
#define KCH 256           // K1: key rows per chunk
#define NCH 8             // K1: key chunks
#define LCH 256           // K1: queries per block
#define NEG_INF (-3.4e38f)

typedef unsigned long long ull;
typedef unsigned int uint;

// ---------------- f32x2 helpers ----------------
__device__ __forceinline__ ull pk2(float a, float b) {
    ull r; asm("mov.b64 %0,{%1,%2};" : "=l"(r) : "f"(a), "f"(b)); return r;
}
__device__ __forceinline__ void upk2(ull v, float& a, float& b) {
    asm("mov.b64 {%0,%1},%2;" : "=f"(a), "=f"(b) : "l"(v));
}
__device__ __forceinline__ ull fma2_(ull a, ull b, ull c) {
    ull d; asm("fma.rn.f32x2 %0,%1,%2,%3;" : "=l"(d) : "l"(a), "l"(b), "l"(c)); return d;
}
__device__ __forceinline__ ull add2_(ull a, ull b) {
    ull d; asm("add.rn.f32x2 %0,%1,%2;" : "=l"(d) : "l"(a), "l"(b)); return d;
}

// ---------------- scratch (device globals; no allocation) ----------------
__device__ uint     g_bidxw[L*S/4];       // per-l sample rows as bytes, sorted by chunk
__device__ uint     g_bcntw[L*2];         // per-l 8 chunk counts as bytes
__device__ float    g_M[NBH*L];           // sparsity metric
__device__ int      g_Mtop[NBH*U];        // top-U query indices per bh
__device__ float    g_Vpart[NBH*SPLIT*D]; // partial V sums
__device__ float2   g_pO2[NBH*SPLIT*U*D/2]; // split attention partial outputs
__device__ float    g_pm[NBH*SPLIT*U];    // split local max
__device__ float    g_pl[NBH*SPLIT*U];    // split local sum-exp

// ---------------- K0: warp-per-query ballot bucketing ----------------
__global__ void __launch_bounds__(256) k0_bucket(const int* __restrict__ idxs) {
    int w = threadIdx.x >> 5, lane = threadIdx.x & 31;
    int l = blockIdx.x * 8 + w;                     // 256 blocks x 8 warps = 2048
    const int* p = idxs + l * S;
    int v0 = p[lane];
    int c0v = v0 >> 8;
    int v1 = 0, c1v = -1;
    if (lane < 8) { v1 = p[32 + lane]; c1v = v1 >> 8; }
    unsigned m0[NCH], m1[NCH];
    int cnt[NCH];
    #pragma unroll
    for (int cc = 0; cc < NCH; cc++) {
        m0[cc] = __ballot_sync(0xffffffffu, c0v == cc);
        m1[cc] = __ballot_sync(0xffffffffu, c1v == cc);
        cnt[cc] = __popc(m0[cc]) + __popc(m1[cc]);
    }
    int basep[NCH];
    int run = 0;
    #pragma unroll
    for (int cc = 0; cc < NCH; cc++) { basep[cc] = run; run += cnt[cc]; }
    unsigned lt = (1u << lane) - 1u;
    unsigned char* bp = (unsigned char*)g_bidxw + l*S;
    int pos0 = basep[c0v] + __popc(m0[c0v] & lt);
    bp[pos0] = (unsigned char)(v0 & 255);
    if (lane < 8) {
        int pos1 = basep[c1v] + __popc(m0[c1v]) + __popc(m1[c1v] & lt);
        bp[pos1] = (unsigned char)(v1 & 255);
    }
    if (lane == 0) {
        g_bcntw[l*2    ] = (uint)cnt[0] | ((uint)cnt[1] << 8) | ((uint)cnt[2] << 16) | ((uint)cnt[3] << 24);
        g_bcntw[l*2 + 1] = (uint)cnt[4] | ((uint)cnt[5] << 8) | ((uint)cnt[6] << 16) | ((uint)cnt[7] << 24);
    }
}

// ---------------- K1: thread-per-query, Q in registers, smem K chunks ----------------
#define SMEM1_BYTES (KCH*D*4 + LCH*S)   // 65536 + 10240 = 75776

__global__ void __launch_bounds__(256, 2) k1_reg(const float* __restrict__ Qg,
                                                 const float* __restrict__ Kg) {
    int bh = blockIdx.x >> 3, lch = blockIdx.x & 7;
    int b = bh >> 3, h = bh & 7;
    int l0 = lch * LCH;
    int t = threadIdx.x, lane = t & 31;
    extern __shared__ float sm[];
    float4* Ks4 = (float4*)sm;                           // 256 rows x 16 float4
    unsigned char* sByte = (unsigned char*)(sm + KCH*D); // 256 x 40 bytes

    int offs[16];
    #pragma unroll
    for (int j = 0; j < 16; j++) offs[j] = (lane + j) & 15;

    // ---- stage Q panel into Ks4 (coalesced), idx bytes into sByte ----
    for (int e = t; e < LCH*16; e += 256) {
        int i = e >> 4, c4 = e & 15;
        Ks4[e] = __ldg((const float4*)(Qg + ((size_t)(b*L + l0 + i)*H + h)*D) + c4);
    }
    uint* sb32 = (uint*)sByte;
    for (int e = t; e < LCH*(S/4); e += 256)
        sb32[e] = g_bidxw[l0*(S/4) + e];
    __syncthreads();

    ull q0[16], q1[16];
    #pragma unroll
    for (int j = 0; j < 16; j++) {
        float4 v = Ks4[t*16 + offs[j]];
        q0[j] = pk2(v.x, v.y);
        q1[j] = pk2(v.z, v.w);
    }
    uint cw0 = g_bcntw[(l0 + t)*2];
    uint cw1 = g_bcntw[(l0 + t)*2 + 1];
    __syncthreads();

    ull z = pk2(0.f, 0.f);
    float lmax = NEG_INF, lsum = 0.f;
    int p0 = t * S;

    for (int c = 0; c < NCH; c++) {
        const float* Kbase = Kg + (size_t)(b*L + c*KCH)*(H*D) + h*D;
        for (int e = t; e < KCH*16; e += 256) {
            int kk = e >> 4, c4 = e & 15;
            Ks4[e] = __ldg((const float4*)(Kbase + (size_t)kk*(H*D)) + c4);
        }
        __syncthreads();

        int cnt = (c < 4) ? (int)((cw0 >> (c*8)) & 255u)
                          : (int)((cw1 >> ((c-4)*8)) & 255u);
        if (cnt) {
            int row = sByte[p0];
            for (int j = 0; j < cnt; j++) {
                int jn = (j + 1 < cnt) ? j + 1 : j;
                int rown = sByte[p0 + jn];             // prefetch next index
                const float4* kp = Ks4 + row*16;
                ull a0 = z, a1 = z, a2 = z, a3 = z;
                #pragma unroll
                for (int g = 0; g < 4; g++) {          // 4 float4 in flight
                    float4 k0 = kp[offs[4*g + 0]];
                    float4 k1 = kp[offs[4*g + 1]];
                    float4 k2 = kp[offs[4*g + 2]];
                    float4 k3 = kp[offs[4*g + 3]];
                    a0 = fma2_(q0[4*g + 0], pk2(k0.x, k0.y), a0);
                    a1 = fma2_(q1[4*g + 0], pk2(k0.z, k0.w), a1);
                    a2 = fma2_(q0[4*g + 1], pk2(k1.x, k1.y), a2);
                    a3 = fma2_(q1[4*g + 1], pk2(k1.z, k1.w), a3);
                    a0 = fma2_(q0[4*g + 2], pk2(k2.x, k2.y), a0);
                    a1 = fma2_(q1[4*g + 2], pk2(k2.z, k2.w), a1);
                    a2 = fma2_(q0[4*g + 3], pk2(k3.x, k3.y), a2);
                    a3 = fma2_(q1[4*g + 3], pk2(k3.z, k3.w), a3);
                }
                a0 = add2_(a0, a1); a2 = add2_(a2, a3); a0 = add2_(a0, a2);
                float lo, hi; upk2(a0, lo, hi);
                float pdot = lo + hi;
                lmax = fmaxf(lmax, pdot);
                lsum += pdot;
                row = rown;
            }
        }
        p0 += cnt;
        __syncthreads();
    }

    g_M[bh*L + l0 + t] = lmax - lsum * (1.0f / S);
}

// ---------------- K2: two-level top-U (warp-local lists, then merge) ----------------
__global__ void __launch_bounds__(256) k2_topk() {
    __shared__ float sv[L];
    __shared__ float wvs[8*U];
    __shared__ int   wis[8*U];
    int bh = blockIdx.x, tid = threadIdx.x;
    int lane = tid & 31, w = tid >> 5;
    for (int i = tid; i < L; i += 256) sv[i] = g_M[bh*L + i];
    __syncthreads();

    // warp w: top-U of slice [w*256, w*256+256), values in registers
    int base = w*256 + lane;
    float v[8];
    #pragma unroll
    for (int t = 0; t < 8; t++) v[t] = sv[base + t*32];
    for (int it = 0; it < U; it++) {
        float bv = v[0]; int bt = 0;
        #pragma unroll
        for (int t = 1; t < 8; t++)
            if (v[t] > bv) { bv = v[t]; bt = t; }     // strict > keeps smallest t (= smallest idx)
        int bi = base + bt*32;
        #pragma unroll
        for (int o = 16; o; o >>= 1) {
            float ov = __shfl_xor_sync(0xffffffffu, bv, o);
            int   oi = __shfl_xor_sync(0xffffffffu, bi, o);
            if (ov > bv || (ov == bv && oi < bi)) { bv = ov; bi = oi; }
        }
        int rel = bi - w*256;
        if ((rel & 31) == lane) v[rel >> 5] = NEG_INF;   // winner's owner invalidates
        if (lane == 0) { wvs[w*U + it] = bv; wis[w*U + it] = bi; }
    }
    __syncthreads();

    // warp 0 merges 8*U = 320 candidates (disjoint indices)
    if (w == 0) {
        float cv[10]; int ci[10];
        #pragma unroll
        for (int r = 0; r < 10; r++) { cv[r] = wvs[lane + 32*r]; ci[r] = wis[lane + 32*r]; }
        for (int it = 0; it < U; it++) {
            float bv = cv[0]; int bi = ci[0];
            #pragma unroll
            for (int r = 1; r < 10; r++)
                if (cv[r] > bv || (cv[r] == bv && ci[r] < bi)) { bv = cv[r]; bi = ci[r]; }
            #pragma unroll
            for (int o = 16; o; o >>= 1) {
                float ov = __shfl_xor_sync(0xffffffffu, bv, o);
                int   oi = __shfl_xor_sync(0xffffffffu, bi, o);
                if (ov > bv || (ov == bv && oi < bi)) { bv = ov; bi = oi; }
            }
            if (lane == 0) g_Mtop[bh*U + it] = bi;
            #pragma unroll
            for (int r = 0; r < 10; r++)
                if (ci[r] == bi) cv[r] = NEG_INF;
        }
    }
}

// ---------------- K3: partial V sums over L-chunks ----------------
__global__ void __launch_bounds__(256) k3_vsum(const float* __restrict__ Vg) {
    int bh = blockIdx.x >> 3, sp = blockIdx.x & 7;
    int b = bh >> 3, h = bh & 7;
    int d  = threadIdx.x & 63;
    int lg = threadIdx.x >> 6;
    const float* base = Vg + (size_t)b*L*(H*D) + h*D + d;
    int l0 = sp*CHUNK + lg;
    float a0 = 0.f, a1 = 0.f;
    #pragma unroll 8
    for (int i = 0; i < CHUNK/8; i++) {
        a0 += base[(size_t)(l0 + i*8    ) * (H*D)];
        a1 += base[(size_t)(l0 + i*8 + 4) * (H*D)];
    }
    __shared__ float red[4][64];
    red[lg][d] = a0 + a1;
    __syncthreads();
    if (threadIdx.x < 64)
        g_Vpart[(bh*SPLIT + sp)*D + threadIdx.x] =
            red[0][threadIdx.x] + red[1][threadIdx.x] + red[2][threadIdx.x] + red[3][threadIdx.x];
}

// ---------------- K4: broadcast V-mean into full output ----------------
__global__ void __launch_bounds__(256) k4_fill(float* __restrict__ out) {
    int b  = blockIdx.x >> 6;
    int r0 = (blockIdx.x & 63) * 32;
    __shared__ __align__(16) float vec[512];
    int tid = threadIdx.x;
    for (int j = tid; j < 512; j += 256) {
        int h = j >> 6, d = j & 63;
        float s = 0.f;
        #pragma unroll
        for (int sp = 0; sp < SPLIT; sp++)
            s += g_Vpart[((b*H + h)*SPLIT + sp)*D + d];
        vec[j] = s * (1.0f / L);
    }
    __syncthreads();
    float4* o4 = (float4*)(out + (size_t)(b*L + r0) * (H*D));
    const float4* v4 = (const float4*)vec;
    for (int e = tid; e < 32*128; e += 256) {
        int r = e >> 7, c = e & 127;
        o4[r*128 + c] = v4[c];
    }
}

// ---------------- K5: split-K sparse attention, f32x2, Qs aliased into Sc ----------------
// smem floats: Ks 256*64 (float2-xor swizzle; K then V) | Sc 40*264 (Qs aliased at Sc base)
#define SCW 264
#define SM5_KS 0
#define SM5_SC 16384
#define SMEM5_BYTES ((16384 + U*SCW) * 4)   // 107776

__global__ void __launch_bounds__(256, 2) k5_attn(const float* __restrict__ Qg,
                                                  const float* __restrict__ Kg,
                                                  const float* __restrict__ Vg) {
    int bh = blockIdx.x >> 3, sp = blockIdx.x & 7;
    int b = bh >> 3, h = bh & 7;
    int tid = threadIdx.x;
    extern __shared__ float sm[];
    float2* Ks2 = (float2*)(sm + SM5_KS);
    float*  Sc  = sm + SM5_SC;
    float*  Qs  = sm + SM5_SC;             // aliased: Qs dead after phase 1
    float2* Qs2 = (float2*)Qs;
    __shared__ int topq[U];

    if (tid < U) topq[tid] = g_Mtop[bh*U + tid];
    __syncthreads();

    // gather selected Q rows; stage K chunk (float2 swizzle: phys2 = kk*32 + (c2 ^ (kk>>3)))
    for (int e = tid; e < U*D; e += 256) {
        int i = e >> 6, d = e & 63;
        Qs[e] = Qg[((size_t)(b*L + topq[i])*H + h)*D + d];
    }
    const float* Kbase = Kg + (size_t)(b*L + sp*CHUNK)*(H*D) + h*D;
    for (int e = tid; e < CHUNK*D/2; e += 256) {
        int kk = e >> 5, c2 = e & 31;
        Ks2[kk*32 + (c2 ^ (kk >> 3))] = *(const float2*)(Kbase + (size_t)kk*(H*D) + c2*2);
    }
    __syncthreads();

    // phase 1: scores = Qs @ Ks^T * scale (5q x 8k per thread, f32x2 over d)
    int qg = tid >> 5, kg = tid & 31;
    ull z2 = pk2(0.f, 0.f);
    ull acc2[5][8];
    #pragma unroll
    for (int i = 0; i < 5; i++)
        #pragma unroll
        for (int j = 0; j < 8; j++) acc2[i][j] = z2;

    #pragma unroll 2
    for (int dd = 0; dd < 32; dd++) {
        ull qv[5], kv[8];
        #pragma unroll
        for (int i = 0; i < 5; i++) { float2 tq = Qs2[(qg*5 + i)*32 + dd]; qv[i] = pk2(tq.x, tq.y); }
        #pragma unroll
        for (int j = 0; j < 8; j++) { float2 tk = Ks2[(kg*8 + j)*32 + (dd ^ kg)]; kv[j] = pk2(tk.x, tk.y); }
        #pragma unroll
        for (int i = 0; i < 5; i++)
            #pragma unroll
            for (int j = 0; j < 8; j++) acc2[i][j] = fma2_(qv[i], kv[j], acc2[i][j]);
    }
    __syncthreads();   // ALL Qs/Ks reads done before Sc (aliased) writes & V load

    #pragma unroll
    for (int i = 0; i < 5; i++) {
        int q = qg*5 + i;
        float s[8];
        #pragma unroll
        for (int j = 0; j < 8; j++) { float lo, hi; upk2(acc2[i][j], lo, hi); s[j] = (lo + hi) * 0.125f; }
        float4* dst = (float4*)(Sc + q*SCW + kg*8);
        dst[0] = make_float4(s[0], s[1], s[2], s[3]);
        dst[1] = make_float4(s[4], s[5], s[6], s[7]);
    }
    // load V into Ks buffer (same swizzle)
    const float* Vbase = Vg + (size_t)(b*L + sp*CHUNK)*(H*D) + h*D;
    for (int e = tid; e < CHUNK*D/2; e += 256) {
        int kk = e >> 5, c2 = e & 31;
        Ks2[kk*32 + (c2 ^ (kk >> 3))] = *(const float2*)(Vbase + (size_t)kk*(H*D) + c2*2);
    }
    __syncthreads();

    // per-warp local softmax on its 5 queries
    int lane = tid & 31;
    #pragma unroll
    for (int i = 0; i < 5; i++) {
        int q = qg*5 + i;
        float vals[8];
        float mv = NEG_INF;
        #pragma unroll
        for (int t = 0; t < 8; t++) {
            vals[t] = Sc[q*SCW + lane + t*32];
            mv = fmaxf(mv, vals[t]);
        }
        #pragma unroll
        for (int o = 16; o; o >>= 1) mv = fmaxf(mv, __shfl_xor_sync(0xffffffffu, mv, o));
        float ssum = 0.f;
        #pragma unroll
        for (int t = 0; t < 8; t++) {
            float ev = __expf(vals[t] - mv);
            Sc[q*SCW + lane + t*32] = ev;
            ssum += ev;
        }
        #pragma unroll
        for (int o = 16; o; o >>= 1) ssum += __shfl_xor_sync(0xffffffffu, ssum, o);
        if (lane == 0) {
            g_pm[(bh*SPLIT + sp)*U + q] = mv;
            g_pl[(bh*SPLIT + sp)*U + q] = ssum;
        }
    }
    __syncthreads();

    // phase 2: partial O = P @ V (4 key-ranges x 5q x 4 d-pairs per thread)
    int kr  = tid >> 6;
    int r   = tid & 63;
    int qg2 = r >> 3, dg = r & 7;
    ull facc[5][4];
    #pragma unroll
    for (int i = 0; i < 5; i++)
        #pragma unroll
        for (int j = 0; j < 4; j++) facc[i][j] = z2;

    #pragma unroll 2
    for (int kl = 0; kl < 64; kl++) {
        int kk = kr*64 + kl;
        ull pv2[5], vv[4];
        #pragma unroll
        for (int i = 0; i < 5; i++) {
            float p = Sc[(qg2*5 + i)*SCW + kk];
            pv2[i] = pk2(p, p);
        }
        int sw = kk >> 3;
        #pragma unroll
        for (int j = 0; j < 4; j++) {
            float2 tv = Ks2[kk*32 + ((dg*4 + j) ^ sw)];
            vv[j] = pk2(tv.x, tv.y);
        }
        #pragma unroll
        for (int i = 0; i < 5; i++)
            #pragma unroll
            for (int j = 0; j < 4; j++) facc[i][j] = fma2_(pv2[i], vv[j], facc[i][j]);
    }
    __syncthreads();   // P reads done; reuse Sc as reduce scratch (4*40*32 float2 = 10240 fl)
    float2* Scr = (float2*)Sc;
    #pragma unroll
    for (int i = 0; i < 5; i++) {
        int q = qg2*5 + i;
        #pragma unroll
        for (int j = 0; j < 4; j++) {
            float lo, hi; upk2(facc[i][j], lo, hi);
            Scr[kr*1280 + q*32 + dg*4 + j] = make_float2(lo, hi);
        }
    }
    __syncthreads();
    float2* pO2 = g_pO2 + (size_t)(bh*SPLIT + sp)*U*D/2;
    for (int e = tid; e < U*D/2; e += 256) {
        float2 a = Scr[e], b2 = Scr[1280 + e], c = Scr[2560 + e], d2 = Scr[3840 + e];
        pO2[e] = make_float2(a.x + b2.x + c.x + d2.x, a.y + b2.y + c.y + d2.y);
    }
}

// ---------------- K6: combine splits + scatter to output ----------------
__global__ void __launch_bounds__(256) k6_combine(float* __restrict__ out) {
    int bh = blockIdx.x;
    int b = bh >> 3, h = bh & 7;
    __shared__ float w[U*SPLIT];
    __shared__ int topq[U];
    int tid = threadIdx.x;
    const float* gpO = (const float*)g_pO2;
    if (tid < U) {
        topq[tid] = g_Mtop[bh*U + tid];
        float pm_[SPLIT], pl_[SPLIT];
        float m = NEG_INF;
        #pragma unroll
        for (int sp = 0; sp < SPLIT; sp++) {
            pm_[sp] = g_pm[(bh*SPLIT + sp)*U + tid];
            pl_[sp] = g_pl[(bh*SPLIT + sp)*U + tid];
            m = fmaxf(m, pm_[sp]);
        }
        float denom = 0.f, e_[SPLIT];
        #pragma unroll
        for (int sp = 0; sp < SPLIT; sp++) {
            e_[sp] = __expf(pm_[sp] - m);
            denom += pl_[sp] * e_[sp];
        }
        float inv = 1.0f / denom;
        #pragma unroll
        for (int sp = 0; sp < SPLIT; sp++) w[tid*SPLIT + sp] = e_[sp] * inv;
    }
    __syncthreads();
    for (int e = tid; e < U*D; e += 256) {
        int q = e >> 6, d = e & 63;
        float s = 0.f;
        #pragma unroll
        for (int sp = 0; sp < SPLIT; sp++)
            s += gpO[((size_t)(bh*SPLIT + sp)*U + q)*D + d] * w[q*SPLIT + sp];
        out[((size_t)(b*L + topq[q])*H + h)*D + d] = s;
    }
}

// ---------------- launch ----------------
extern "C" void kernel_launch(void* const* d_in, const int* in_sizes, int n_in,
                              void* d_out, int out_size) {
    const float* Q   = (const float*)d_in[0];
    const float* K   = (const float*)d_in[1];
    const float* V   = (const float*)d_in[2];
    const int*  idxs = (const int*)d_in[3];
    float* out = (float*)d_out;

    cudaFuncSetAttribute(k1_reg,  cudaFuncAttributeMaxDynamicSharedMemorySize, SMEM1_BYTES);
    cudaFuncSetAttribute(k5_attn, cudaFuncAttributeMaxDynamicSharedMemorySize, SMEM5_BYTES);

    // k1 stays 4th launch for the ncu capture slot
    k0_bucket <<<L/8,       256>>>(idxs);
    k3_vsum   <<<NBH*SPLIT, 256>>>(V);
    k4_fill   <<<B*64,      256>>>(out);
    k1_reg    <<<NBH*8,     256, SMEM1_BYTES>>>(Q, K);
    k2_topk   <<<NBH,       256>>>();
    k5_attn   <<<NBH*SPLIT, 256, SMEM5_BYTES>>>(Q, K, V);
    k6_combine<<<NBH,       256>>>(out);
}